// round 16
// baseline (speedup 1.0000x reference)
#include <cuda_runtime.h>
#include <cuda_bf16.h>
#include <math.h>
#include <stdint.h>

// x[8,2048,1024] fp32, prototypes[64,1024] fp32, attn_mask[8,2048] int32.
#define DDIM 1024
#define NEXP 64
#define SEQ  2048
#define TM   128
#define KC   64
#define KSPLIT 2
#define KHALF (DDIM / KSPLIT)            // 512
#define NCH  (KHALF / KC)                // 8 chunks per CTA
#define NT   256
#define MAXTOK 16384
#define THR 1e-5f            // flag threshold on summed (x3) logit gaps
#define TOKPB 64             // tokens per topk block

// smem: padded rows of 144 B (36 words; 36 mod 32 = 4 -> every 8-row x 16B
// ldmatrix phase hits 32 distinct banks). SINGLE buffer.
#define RSTRIDE 144
#define AH_OFF 0
#define AM_OFF 18432
#define BH_OFF 36864
#define BM_OFF 46080
#define BUFSZ  55296
#define SMEM_BUF0 1024
#define SMEM_TOTAL (SMEM_BUF0 + BUFSZ)   // 56320 -> 2 CTAs/SM

__device__ float g_part[KSPLIT * MAXTOK * NEXP];   // unnormalized partial dots
__device__ float g_sumsq[KSPLIT * MAXTOK];         // partial row sum-of-squares

// ---------------- helpers ----------------
__device__ __forceinline__ void split2(float x, __nv_bfloat16& h, __nv_bfloat16& m) {
    h = __float2bfloat16(x);
    m = __float2bfloat16(x - __bfloat162float(h));
}
__device__ __forceinline__ uint32_t packbf(__nv_bfloat16 a, __nv_bfloat16 b) {
    __nv_bfloat162 v(a, b);
    return *reinterpret_cast<uint32_t*>(&v);
}
__device__ __forceinline__ void ldm4(uint32_t* r, const void* p) {
    uint32_t a = (uint32_t)__cvta_generic_to_shared(p);
    asm volatile("ldmatrix.sync.aligned.m8n8.x4.shared.b16 {%0,%1,%2,%3}, [%4];"
                 : "=r"(r[0]), "=r"(r[1]), "=r"(r[2]), "=r"(r[3]) : "r"(a));
}
__device__ __forceinline__ void mma_bf16(float* d, const uint32_t* a,
                                         uint32_t b0, uint32_t b1) {
    asm volatile(
        "mma.sync.aligned.m16n8k16.row.col.f32.bf16.bf16.f32 "
        "{%0,%1,%2,%3}, {%4,%5,%6,%7}, {%8,%9}, {%0,%1,%2,%3};"
        : "+f"(d[0]), "+f"(d[1]), "+f"(d[2]), "+f"(d[3])
        : "r"(a[0]), "r"(a[1]), "r"(a[2]), "r"(a[3]), "r"(b0), "r"(b1));
}
__device__ __forceinline__ bool better(float v, int vi, float w, int wi) {
    return (v > w) || (v == w && vi < wi);
}

// ---------------------------------------------------------------------------
// GEMM: bf16x3 (hh, hm, mh) on tensor cores. Grid = 128 tiles x 2 K-halves.
// TM=128 tokens / CTA over K=512. 8 warps: warp = m32 (wid&3) x n32 (wid>>2).
// Single smem buffer, 2 syncs/chunk; 2 CTAs/SM cover the staging latency.
// Writes UNNORMALIZED partial dots + partial sumsq; topk normalizes.
// ---------------------------------------------------------------------------
__global__ __launch_bounds__(NT, 2) void gemm_kernel(const float* __restrict__ x,
                                                     const float* __restrict__ proto) {
    extern __shared__ char smem[];
    char* buf = smem + SMEM_BUF0;

    const int t = threadIdx.x;
    const int wid = t >> 5, lane = t & 31;
    const int tile = blockIdx.x >> 1, khalf = blockIdx.x & 1;
    const size_t blockRow = (size_t)tile * TM;
    const int kbase = khalf * KHALF;

    // staging maps
    const int arow = t >> 1, ahalf = t & 1;
    const int pe = t >> 2, pq = t & 3;
    const float* xrow = x + (blockRow + arow) * DDIM + kbase + ahalf * 32;
    const float* prow = proto + (size_t)pe * DDIM + kbase + pq * 16;

    float acc[2][2][2][4];                 // [mt][l][j][quad]
#pragma unroll
    for (int a = 0; a < 2; a++)
#pragma unroll
        for (int b = 0; b < 2; b++)
#pragma unroll
            for (int c2 = 0; c2 < 2; c2++)
#pragma unroll
                for (int q = 0; q < 4; q++) acc[a][b][c2][q] = 0.f;

    float srow = 0.f;

    // compute-phase mapping: warp = m32 x n32
    const int mgrp = wid & 3, ngrp = wid >> 2;
    const int M0 = mgrp * 32;
    const uint32_t a_off = (uint32_t)(M0 + (lane & 15)) * RSTRIDE + ((lane >> 4) << 4);
    const uint32_t b_n   = (lane & 7) + ((lane >> 4) << 3);
    const uint32_t b_kb  = ((lane >> 3) & 1) << 4;

    for (int c = 0; c < NCH; c++) {
        if (c > 0) __syncthreads();        // prev compute done; buffer reusable

        // ---- stage A: 32 floats -> h/m ----
        {
            const uint32_t ad = (uint32_t)arow * RSTRIDE + ahalf * 64;
            const float4* src = reinterpret_cast<const float4*>(xrow + c * KC);
#pragma unroll
            for (int g = 0; g < 4; g++) {
                float4 v0 = src[2 * g], v1 = src[2 * g + 1];
                float f[8] = { v0.x, v0.y, v0.z, v0.w, v1.x, v1.y, v1.z, v1.w };
                __nv_bfloat16 h[8], m[8];
#pragma unroll
                for (int e = 0; e < 8; e++) {
                    srow += f[e] * f[e];
                    split2(f[e], h[e], m[e]);
                }
                *reinterpret_cast<uint4*>(buf + AH_OFF + ad + g * 16) =
                    make_uint4(packbf(h[0], h[1]), packbf(h[2], h[3]),
                               packbf(h[4], h[5]), packbf(h[6], h[7]));
                *reinterpret_cast<uint4*>(buf + AM_OFF + ad + g * 16) =
                    make_uint4(packbf(m[0], m[1]), packbf(m[2], m[3]),
                               packbf(m[4], m[5]), packbf(m[6], m[7]));
            }
        }
        // ---- stage B: 16 floats -> h/m ----
        {
            const uint32_t pd = (uint32_t)pe * RSTRIDE + pq * 32;
            const float4* src = reinterpret_cast<const float4*>(prow + c * KC);
#pragma unroll
            for (int g = 0; g < 2; g++) {
                float4 v0 = src[2 * g], v1 = src[2 * g + 1];
                float f[8] = { v0.x, v0.y, v0.z, v0.w, v1.x, v1.y, v1.z, v1.w };
                __nv_bfloat16 h[8], m[8];
#pragma unroll
                for (int e = 0; e < 8; e++) split2(f[e], h[e], m[e]);
                *reinterpret_cast<uint4*>(buf + BH_OFF + pd + g * 16) =
                    make_uint4(packbf(h[0], h[1]), packbf(h[2], h[3]),
                               packbf(h[4], h[5]), packbf(h[6], h[7]));
                *reinterpret_cast<uint4*>(buf + BM_OFF + pd + g * 16) =
                    make_uint4(packbf(m[0], m[1]), packbf(m[2], m[3]),
                               packbf(m[4], m[5]), packbf(m[6], m[7]));
            }
        }
        __syncthreads();

        // ---- compute: 4 k16-steps; warp covers m32 x n32 ----
#pragma unroll
        for (int ks = 0; ks < 4; ks++) {
            const uint32_t ksb = ks * 32;
            uint32_t ah0[4], am0[4], ah1[4], am1[4];
            ldm4(ah0, buf + AH_OFF + a_off + ksb);
            ldm4(ah1, buf + AH_OFF + a_off + 16 * RSTRIDE + ksb);
            ldm4(am0, buf + AM_OFF + a_off + ksb);
            ldm4(am1, buf + AM_OFF + a_off + 16 * RSTRIDE + ksb);
#pragma unroll
            for (int l = 0; l < 2; l++) {
                const int ntp = ngrp * 2 + l;
                const uint32_t bo = (uint32_t)(ntp * 16 + b_n) * RSTRIDE + b_kb + ksb;
                uint32_t bh[4], bm[4];
                ldm4(bh, buf + BH_OFF + bo);
                ldm4(bm, buf + BM_OFF + bo);
#pragma unroll
                for (int j = 0; j < 2; j++) {
                    mma_bf16(acc[0][l][j], ah0, bh[2 * j], bh[2 * j + 1]);
                    mma_bf16(acc[1][l][j], ah1, bh[2 * j], bh[2 * j + 1]);
                    mma_bf16(acc[0][l][j], am0, bh[2 * j], bh[2 * j + 1]);
                    mma_bf16(acc[1][l][j], am1, bh[2 * j], bh[2 * j + 1]);
                    mma_bf16(acc[0][l][j], ah0, bm[2 * j], bm[2 * j + 1]);
                    mma_bf16(acc[1][l][j], ah1, bm[2 * j], bm[2 * j + 1]);
                }
            }
        }
    }

    // ---- partial row sumsq (threads t, t^1 share a row) ----
    srow += __shfl_xor_sync(0xffffffffu, srow, 1);
    if ((t & 1) == 0)
        g_sumsq[khalf * MAXTOK + blockRow + arow] = srow;

    // ---- epilogue: raw partial dots ----
    {
        float* part = g_part + (size_t)khalf * MAXTOK * NEXP;
        const int g = lane >> 2, cq2 = 2 * (lane & 3);
#pragma unroll
        for (int mt = 0; mt < 2; mt++) {
            int row0 = M0 + mt * 16 + g;
            float* d0 = &part[(blockRow + row0) * NEXP];
            float* d1 = &part[(blockRow + row0 + 8) * NEXP];
#pragma unroll
            for (int l = 0; l < 2; l++)
#pragma unroll
                for (int j = 0; j < 2; j++) {
                    int col = ngrp * 32 + l * 16 + j * 8 + cq2;
                    float* a = acc[mt][l][j];
                    *reinterpret_cast<float2*>(d0 + col) = make_float2(a[0], a[1]);
                    *reinterpret_cast<float2*>(d1 + col) = make_float2(a[2], a[3]);
                }
        }
    }
}

// ---------------------------------------------------------------------------
// Topk + inline fixup: block = 64 tokens (4 threads each). Sums K-split
// partials, normalizes, window-3, top-3 with near-tie flagging into SMEM;
// after a barrier the block recomputes its flagged tokens exactly in fp32.
// ---------------------------------------------------------------------------
__device__ __forceinline__ void merge3(float& a1, int& i1, float& a2, int& i2,
                                       float& a3, int& i3,
                                       float b1, int j1, float b2, int j2,
                                       float b3, int j3) {
    if (!better(a1, i1, b1, j1)) {
        float tv; int ti;
        tv = a1; a1 = b1; b1 = tv; ti = i1; i1 = j1; j1 = ti;
        tv = a2; a2 = b2; b2 = tv; ti = i2; i2 = j2; j2 = ti;
        tv = a3; a3 = b3; b3 = tv; ti = i3; i3 = j3; j3 = ti;
    }
    if (better(a2, i2, b1, j1)) {
        if (!better(a3, i3, b1, j1)) { a3 = b1; i3 = j1; }
    } else {
        float na3; int ni3;
        if (better(a2, i2, b2, j2)) { na3 = a2; ni3 = i2; }
        else                        { na3 = b2; ni3 = j2; }
        a2 = b1; i2 = j1; a3 = na3; i3 = ni3;
    }
}

__global__ __launch_bounds__(256) void topk_kernel(const float* __restrict__ x,
                                                   const float* __restrict__ proto,
                                                   float* __restrict__ out,
                                                   int ntok, int out_size) {
    // 16B-aligned big arrays FIRST (float4 access), small scalars after.
    __shared__ __align__(16) float xs[3][DDIM];
    __shared__ float invn_s[3];
    __shared__ float sl[NEXP];
    __shared__ int s_list[TOKPB];
    __shared__ int s_cnt;

    const int t = threadIdx.x;
    if (t == 0) s_cnt = 0;
    __syncthreads();

    // ---- main pass: 4 threads per token ----
    {
        int tok = blockIdx.x * TOKPB + (t >> 2);
        int tq = t & 3;
        if (tok < ntok) {
            int b = tok / SEQ, s = tok - b * SEQ;
            int rows[3] = { tok,
                            b * SEQ + (s >= 1 ? s - 1 : 0),
                            b * SEQ + (s >= 2 ? s - 2 : 0) };

            float sv[16];
#pragma unroll
            for (int e = 0; e < 16; e++) sv[e] = 0.f;

#pragma unroll
            for (int j = 0; j < 3; j++) {
                int r = rows[j];
                float ss = g_sumsq[r] + g_sumsq[MAXTOK + r];
                float in = 1.0f / fmaxf(sqrtf(ss), 1e-8f);
                const float4* p0 = reinterpret_cast<const float4*>(
                    &g_part[(size_t)r * NEXP + tq * 16]);
                const float4* p1 = reinterpret_cast<const float4*>(
                    &g_part[(size_t)MAXTOK * NEXP + (size_t)r * NEXP + tq * 16]);
#pragma unroll
                for (int g = 0; g < 4; g++) {
                    float4 u = p0[g], v = p1[g];
                    sv[4 * g + 0] += (u.x + v.x) * in;
                    sv[4 * g + 1] += (u.y + v.y) * in;
                    sv[4 * g + 2] += (u.z + v.z) * in;
                    sv[4 * g + 3] += (u.w + v.w) * in;
                }
            }

            float a1 = -1e30f, a2 = -1e30f, a3 = -1e30f;
            int i1 = 64, i2 = 64, i3 = 64;
#pragma unroll
            for (int e = 0; e < 16; e++) {
                float val = sv[e];
                int idx = tq * 16 + e;
                if (val > a1) { a3 = a2; i3 = i2; a2 = a1; i2 = i1; a1 = val; i1 = idx; }
                else if (val > a2) { a3 = a2; i3 = i2; a2 = val; i2 = idx; }
                else if (val > a3) { a3 = val; i3 = idx; }
            }
#pragma unroll
            for (int off = 1; off <= 2; off <<= 1) {
                float b1 = __shfl_xor_sync(0xffffffffu, a1, off);
                int   j1 = __shfl_xor_sync(0xffffffffu, i1, off);
                float b2 = __shfl_xor_sync(0xffffffffu, a2, off);
                int   j2 = __shfl_xor_sync(0xffffffffu, i2, off);
                float b3 = __shfl_xor_sync(0xffffffffu, a3, off);
                int   j3 = __shfl_xor_sync(0xffffffffu, i3, off);
                merge3(a1, i1, a2, i2, a3, i3, b1, j1, b2, j2, b3, j3);
            }

            if (tq == 0) {
                float e2 = expf((a2 - a1) * (1.0f / 3.0f));
                float inv = 1.0f / (1.0f + e2);
                size_t t0 = (size_t)tok;
                if (out_size >= 4 * ntok) {
                    out[t0 * 2 + 0] = (float)i1;
                    out[t0 * 2 + 1] = (float)i2;
                    out[(size_t)ntok * 2 + t0 * 2 + 0] = inv;
                    out[(size_t)ntok * 2 + t0 * 2 + 1] = e2 * inv;
                } else if (out_size >= 2 * ntok) {
                    out[t0 * 2 + 0] = (float)i1;
                    out[t0 * 2 + 1] = (float)i2;
                }
                if ((a1 - a2 < THR) || (a2 - a3 < THR)) {
                    int fi = atomicAdd(&s_cnt, 1);
                    s_list[fi] = tok;
                }
            }
        }
    }
    __syncthreads();

    // ---- inline exact fixup of this block's flagged tokens ----
    const int cnt = s_cnt;
    const int wid = t >> 5, lane = t & 31;
    for (int f = 0; f < cnt; f++) {
        int tok = s_list[f];
        int b = tok / SEQ, s = tok - b * SEQ;
        int rows[3] = { s, (s >= 1 ? s - 1 : 0), (s >= 2 ? s - 2 : 0) };

#pragma unroll
        for (int j = 0; j < 3; j++) {
            int fl = t + j * 256;
            int row = fl >> 8, col = fl & 255;
            *reinterpret_cast<float4*>(&xs[row][col * 4]) =
                *reinterpret_cast<const float4*>(
                    x + ((size_t)b * SEQ + rows[row]) * DDIM + col * 4);
        }
        __syncthreads();

        if (wid < 3) {
            float ssum = 0.f;
#pragma unroll
            for (int k2 = 0; k2 < DDIM / 32; k2++) {
                float v = xs[wid][lane + 32 * k2];
                ssum += v * v;
            }
#pragma unroll
            for (int off = 16; off; off >>= 1)
                ssum += __shfl_xor_sync(0xffffffffu, ssum, off);
            if (lane == 0) invn_s[wid] = 1.0f / fmaxf(sqrtf(ssum), 1e-8f);
        }
        __syncthreads();

        float in0 = invn_s[0], in1 = invn_s[1], in2 = invn_s[2];
#pragma unroll
        for (int e = 0; e < 8; e++) {
            int ee = wid * 8 + e;
            const float* pr = proto + (size_t)ee * DDIM;
            float d0 = 0.f, d1 = 0.f, d2 = 0.f;
            for (int k2 = lane; k2 < DDIM; k2 += 32) {
                float pv = pr[k2];
                d0 += xs[0][k2] * pv;
                d1 += xs[1][k2] * pv;
                d2 += xs[2][k2] * pv;
            }
#pragma unroll
            for (int off = 16; off; off >>= 1) {
                d0 += __shfl_xor_sync(0xffffffffu, d0, off);
                d1 += __shfl_xor_sync(0xffffffffu, d1, off);
                d2 += __shfl_xor_sync(0xffffffffu, d2, off);
            }
            if (lane == 0) sl[ee] = d0 * in0 + d1 * in1 + d2 * in2;
        }
        __syncthreads();

        if (t == 0) {
            float a1 = -1e30f, a2 = -1e30f;
            int i1 = 0, i2 = 0;
#pragma unroll
            for (int e = 0; e < NEXP; e++) {
                float v = sl[e];
                if (v > a1) { a2 = a1; i2 = i1; a1 = v; i1 = e; }
                else if (v > a2) { a2 = v; i2 = e; }
            }
            float e2 = expf((a2 - a1) * (1.0f / 3.0f));
            float inv = 1.0f / (1.0f + e2);
            size_t t0 = (size_t)tok;
            if (out_size >= 4 * ntok) {
                out[t0 * 2 + 0] = (float)i1;
                out[t0 * 2 + 1] = (float)i2;
                out[(size_t)ntok * 2 + t0 * 2 + 0] = inv;
                out[(size_t)ntok * 2 + t0 * 2 + 1] = e2 * inv;
            } else if (out_size >= 2 * ntok) {
                out[t0 * 2 + 0] = (float)i1;
                out[t0 * 2 + 1] = (float)i2;
            }
        }
        __syncthreads();
    }
}

// ---------------------------------------------------------------------------
extern "C" void kernel_launch(void* const* d_in, const int* in_sizes, int n_in,
                              void* d_out, int out_size) {
    const float* x     = (const float*)d_in[0];
    const float* proto = (const float*)d_in[1];
    int ntok = in_sizes[2];
    if (ntok > MAXTOK) ntok = MAXTOK;
    float* out = (float*)d_out;

    cudaFuncSetAttribute(gemm_kernel,
                         cudaFuncAttributeMaxDynamicSharedMemorySize, SMEM_TOTAL);

    gemm_kernel<<<(ntok / TM) * KSPLIT, NT, SMEM_TOTAL>>>(x, proto);
    topk_kernel<<<(ntok + TOKPB - 1) / TOKPB, 256>>>(x, proto, out, ntok, out_size);
}

// round 17
// speedup vs baseline: 1.2490x; 1.2490x over previous
#include <cuda_runtime.h>
#include <cuda_bf16.h>
#include <math.h>
#include <stdint.h>

// x[8,2048,1024] fp32, prototypes[64,1024] fp32, attn_mask[8,2048] int32.
#define DDIM 1024
#define NEXP 64
#define SEQ  2048
#define TM   128
#define KC   64
#define KSPLIT 2
#define KHALF (DDIM / KSPLIT)            // 512
#define NCH  (KHALF / KC)                // 8 chunks per CTA
#define NT   256
#define MAXTOK 16384
#define MAXFLAG 16384
#define THR 1e-5f            // flag threshold on summed (x3) logit gaps
#define TOKPB 64             // tokens per topk block (divides SEQ)

// smem: padded rows of 144 B (36 words; 36 mod 32 = 4 -> every 8-row x 16B
// ldmatrix phase hits 32 distinct banks). SINGLE buffer.
#define RSTRIDE 144
#define AH_OFF 0
#define AM_OFF 18432
#define BH_OFF 36864
#define BM_OFF 46080
#define BUFSZ  55296
#define SMEM_BUF0 1024
#define SMEM_TOTAL (SMEM_BUF0 + BUFSZ)   // 56320 -> 2 CTAs/SM

#define LSTRIDE 68           // topk smem row stride (68 mod 32 = 4)

__device__ float g_part[KSPLIT * MAXTOK * NEXP];   // unnormalized partial dots
__device__ float g_sumsq[KSPLIT * MAXTOK];         // partial row sum-of-squares
__device__ int g_flagcnt;
__device__ int g_flaglist[MAXFLAG];

// ---------------- helpers ----------------
__device__ __forceinline__ void split2(float x, __nv_bfloat16& h, __nv_bfloat16& m) {
    h = __float2bfloat16(x);
    m = __float2bfloat16(x - __bfloat162float(h));
}
__device__ __forceinline__ uint32_t packbf(__nv_bfloat16 a, __nv_bfloat16 b) {
    __nv_bfloat162 v(a, b);
    return *reinterpret_cast<uint32_t*>(&v);
}
__device__ __forceinline__ void ldm4(uint32_t* r, const void* p) {
    uint32_t a = (uint32_t)__cvta_generic_to_shared(p);
    asm volatile("ldmatrix.sync.aligned.m8n8.x4.shared.b16 {%0,%1,%2,%3}, [%4];"
                 : "=r"(r[0]), "=r"(r[1]), "=r"(r[2]), "=r"(r[3]) : "r"(a));
}
__device__ __forceinline__ void mma_bf16(float* d, const uint32_t* a,
                                         uint32_t b0, uint32_t b1) {
    asm volatile(
        "mma.sync.aligned.m16n8k16.row.col.f32.bf16.bf16.f32 "
        "{%0,%1,%2,%3}, {%4,%5,%6,%7}, {%8,%9}, {%0,%1,%2,%3};"
        : "+f"(d[0]), "+f"(d[1]), "+f"(d[2]), "+f"(d[3])
        : "r"(a[0]), "r"(a[1]), "r"(a[2]), "r"(a[3]), "r"(b0), "r"(b1));
}
__device__ __forceinline__ bool better(float v, int vi, float w, int wi) {
    return (v > w) || (v == w && vi < wi);
}

// ---------------------------------------------------------------------------
// GEMM: bf16x3 (hh, hm, mh) on tensor cores. Grid = 128 tiles x 2 K-halves.
// (unchanged from R14 — 40.5us, protected)
// ---------------------------------------------------------------------------
__global__ __launch_bounds__(NT, 2) void gemm_kernel(const float* __restrict__ x,
                                                     const float* __restrict__ proto) {
    extern __shared__ char smem[];
    char* buf = smem + SMEM_BUF0;

    const int t = threadIdx.x;
    const int wid = t >> 5, lane = t & 31;
    const int tile = blockIdx.x >> 1, khalf = blockIdx.x & 1;
    const size_t blockRow = (size_t)tile * TM;
    const int kbase = khalf * KHALF;

    if (blockIdx.x == 0 && t == 0) g_flagcnt = 0;   // reset for this replay

    // staging maps
    const int arow = t >> 1, ahalf = t & 1;
    const int pe = t >> 2, pq = t & 3;
    const float* xrow = x + (blockRow + arow) * DDIM + kbase + ahalf * 32;
    const float* prow = proto + (size_t)pe * DDIM + kbase + pq * 16;

    float acc[2][2][2][4];
#pragma unroll
    for (int a = 0; a < 2; a++)
#pragma unroll
        for (int b = 0; b < 2; b++)
#pragma unroll
            for (int c2 = 0; c2 < 2; c2++)
#pragma unroll
                for (int q = 0; q < 4; q++) acc[a][b][c2][q] = 0.f;

    float srow = 0.f;

    const int mgrp = wid & 3, ngrp = wid >> 2;
    const int M0 = mgrp * 32;
    const uint32_t a_off = (uint32_t)(M0 + (lane & 15)) * RSTRIDE + ((lane >> 4) << 4);
    const uint32_t b_n   = (lane & 7) + ((lane >> 4) << 3);
    const uint32_t b_kb  = ((lane >> 3) & 1) << 4;

    for (int c = 0; c < NCH; c++) {
        if (c > 0) __syncthreads();

        {   // stage A: 32 floats -> h/m
            const uint32_t ad = (uint32_t)arow * RSTRIDE + ahalf * 64;
            const float4* src = reinterpret_cast<const float4*>(xrow + c * KC);
#pragma unroll
            for (int g = 0; g < 4; g++) {
                float4 v0 = src[2 * g], v1 = src[2 * g + 1];
                float f[8] = { v0.x, v0.y, v0.z, v0.w, v1.x, v1.y, v1.z, v1.w };
                __nv_bfloat16 h[8], m[8];
#pragma unroll
                for (int e = 0; e < 8; e++) {
                    srow += f[e] * f[e];
                    split2(f[e], h[e], m[e]);
                }
                *reinterpret_cast<uint4*>(buf + AH_OFF + ad + g * 16) =
                    make_uint4(packbf(h[0], h[1]), packbf(h[2], h[3]),
                               packbf(h[4], h[5]), packbf(h[6], h[7]));
                *reinterpret_cast<uint4*>(buf + AM_OFF + ad + g * 16) =
                    make_uint4(packbf(m[0], m[1]), packbf(m[2], m[3]),
                               packbf(m[4], m[5]), packbf(m[6], m[7]));
            }
        }
        {   // stage B: 16 floats -> h/m
            const uint32_t pd = (uint32_t)pe * RSTRIDE + pq * 32;
            const float4* src = reinterpret_cast<const float4*>(prow + c * KC);
#pragma unroll
            for (int g = 0; g < 2; g++) {
                float4 v0 = src[2 * g], v1 = src[2 * g + 1];
                float f[8] = { v0.x, v0.y, v0.z, v0.w, v1.x, v1.y, v1.z, v1.w };
                __nv_bfloat16 h[8], m[8];
#pragma unroll
                for (int e = 0; e < 8; e++) split2(f[e], h[e], m[e]);
                *reinterpret_cast<uint4*>(buf + BH_OFF + pd + g * 16) =
                    make_uint4(packbf(h[0], h[1]), packbf(h[2], h[3]),
                               packbf(h[4], h[5]), packbf(h[6], h[7]));
                *reinterpret_cast<uint4*>(buf + BM_OFF + pd + g * 16) =
                    make_uint4(packbf(m[0], m[1]), packbf(m[2], m[3]),
                               packbf(m[4], m[5]), packbf(m[6], m[7]));
            }
        }
        __syncthreads();

#pragma unroll
        for (int ks = 0; ks < 4; ks++) {
            const uint32_t ksb = ks * 32;
            uint32_t ah0[4], am0[4], ah1[4], am1[4];
            ldm4(ah0, buf + AH_OFF + a_off + ksb);
            ldm4(ah1, buf + AH_OFF + a_off + 16 * RSTRIDE + ksb);
            ldm4(am0, buf + AM_OFF + a_off + ksb);
            ldm4(am1, buf + AM_OFF + a_off + 16 * RSTRIDE + ksb);
#pragma unroll
            for (int l = 0; l < 2; l++) {
                const int ntp = ngrp * 2 + l;
                const uint32_t bo = (uint32_t)(ntp * 16 + b_n) * RSTRIDE + b_kb + ksb;
                uint32_t bh[4], bm[4];
                ldm4(bh, buf + BH_OFF + bo);
                ldm4(bm, buf + BM_OFF + bo);
#pragma unroll
                for (int j = 0; j < 2; j++) {
                    mma_bf16(acc[0][l][j], ah0, bh[2 * j], bh[2 * j + 1]);
                    mma_bf16(acc[1][l][j], ah1, bh[2 * j], bh[2 * j + 1]);
                    mma_bf16(acc[0][l][j], am0, bh[2 * j], bh[2 * j + 1]);
                    mma_bf16(acc[1][l][j], am1, bh[2 * j], bh[2 * j + 1]);
                    mma_bf16(acc[0][l][j], ah0, bm[2 * j], bm[2 * j + 1]);
                    mma_bf16(acc[1][l][j], ah1, bm[2 * j], bm[2 * j + 1]);
                }
            }
        }
    }

    srow += __shfl_xor_sync(0xffffffffu, srow, 1);
    if ((t & 1) == 0)
        g_sumsq[khalf * MAXTOK + blockRow + arow] = srow;

    {
        float* part = g_part + (size_t)khalf * MAXTOK * NEXP;
        const int g = lane >> 2, cq2 = 2 * (lane & 3);
#pragma unroll
        for (int mt = 0; mt < 2; mt++) {
            int row0 = M0 + mt * 16 + g;
            float* d0 = &part[(blockRow + row0) * NEXP];
            float* d1 = &part[(blockRow + row0 + 8) * NEXP];
#pragma unroll
            for (int l = 0; l < 2; l++)
#pragma unroll
                for (int j = 0; j < 2; j++) {
                    int col = ngrp * 32 + l * 16 + j * 8 + cq2;
                    float* a = acc[mt][l][j];
                    *reinterpret_cast<float2*>(d0 + col) = make_float2(a[0], a[1]);
                    *reinterpret_cast<float2*>(d1 + col) = make_float2(a[2], a[3]);
                }
        }
    }
}

// ---------------------------------------------------------------------------
// Topk v2: block = 64 tokens. Stage the 66 normalized logit rows (K-halves
// summed, rsqrt applied) into padded smem ONCE; window-3 + top-3 from smem.
// Near-ties flagged to global list for the standalone fixup kernel.
// ---------------------------------------------------------------------------
__device__ __forceinline__ void merge3(float& a1, int& i1, float& a2, int& i2,
                                       float& a3, int& i3,
                                       float b1, int j1, float b2, int j2,
                                       float b3, int j3) {
    if (!better(a1, i1, b1, j1)) {
        float tv; int ti;
        tv = a1; a1 = b1; b1 = tv; ti = i1; i1 = j1; j1 = ti;
        tv = a2; a2 = b2; b2 = tv; ti = i2; i2 = j2; j2 = ti;
        tv = a3; a3 = b3; b3 = tv; ti = i3; i3 = j3; j3 = ti;
    }
    if (better(a2, i2, b1, j1)) {
        if (!better(a3, i3, b1, j1)) { a3 = b1; i3 = j1; }
    } else {
        float na3; int ni3;
        if (better(a2, i2, b2, j2)) { na3 = a2; ni3 = i2; }
        else                        { na3 = b2; ni3 = j2; }
        a2 = b1; i2 = j1; a3 = na3; i3 = ni3;
    }
}

__global__ __launch_bounds__(256) void topk_kernel(float* __restrict__ out,
                                                   int ntok, int out_size) {
    __shared__ __align__(16) float srows[TOKPB + 2][LSTRIDE];
    __shared__ float invn_sh[TOKPB + 2];

    const int t = threadIdx.x;
    const int base = blockIdx.x * TOKPB;          // block never spans a batch
    const int b = base / SEQ;
    const int sbase = base - b * SEQ;

    // per-row inverse norms (rows j = -2..63 clamped to batch start)
    if (t < TOKPB + 2) {
        int sc = sbase + t - 2; if (sc < 0) sc = 0;
        int r = b * SEQ + sc;
        invn_sh[t] = 1.0f / fmaxf(sqrtf(g_sumsq[r] + g_sumsq[MAXTOK + r]), 1e-8f);
    }
    __syncthreads();

    // stage normalized rows: 66 rows x 16 float4 = 1056 tasks
    for (int idx = t; idx < (TOKPB + 2) * 16; idx += 256) {
        int j = idx >> 4, q = idx & 15;
        int sc = sbase + j - 2; if (sc < 0) sc = 0;
        size_t r = (size_t)(b * SEQ + sc);
        float in = invn_sh[j];
        float4 u = *reinterpret_cast<const float4*>(&g_part[r * NEXP + q * 4]);
        float4 v = *reinterpret_cast<const float4*>(
            &g_part[(size_t)MAXTOK * NEXP + r * NEXP + q * 4]);
        *reinterpret_cast<float4*>(&srows[j][q * 4]) =
            make_float4((u.x + v.x) * in, (u.y + v.y) * in,
                        (u.z + v.z) * in, (u.w + v.w) * in);
    }
    __syncthreads();

    // window-3 + top-3: 4 threads per token, 16 experts each
    {
        const int w = t >> 2;                      // token within block
        const int tq = t & 3;
        const int tok = base + w;
        if (tok < ntok) {
            const float* r0 = &srows[w + 2][tq * 16];
            const float* r1 = &srows[w + 1][tq * 16];
            const float* r2 = &srows[w + 0][tq * 16];

            float a1 = -1e30f, a2 = -1e30f, a3 = -1e30f;
            int i1 = 64, i2 = 64, i3 = 64;
#pragma unroll
            for (int e = 0; e < 16; e++) {
                float val = r0[e] + r1[e] + r2[e];
                int idx = tq * 16 + e;
                if (val > a1) { a3 = a2; i3 = i2; a2 = a1; i2 = i1; a1 = val; i1 = idx; }
                else if (val > a2) { a3 = a2; i3 = i2; a2 = val; i2 = idx; }
                else if (val > a3) { a3 = val; i3 = idx; }
            }
#pragma unroll
            for (int off = 1; off <= 2; off <<= 1) {
                float b1 = __shfl_xor_sync(0xffffffffu, a1, off);
                int   j1 = __shfl_xor_sync(0xffffffffu, i1, off);
                float b2 = __shfl_xor_sync(0xffffffffu, a2, off);
                int   j2 = __shfl_xor_sync(0xffffffffu, i2, off);
                float b3 = __shfl_xor_sync(0xffffffffu, a3, off);
                int   j3 = __shfl_xor_sync(0xffffffffu, i3, off);
                merge3(a1, i1, a2, i2, a3, i3, b1, j1, b2, j2, b3, j3);
            }

            if (tq == 0) {
                float e2 = expf((a2 - a1) * (1.0f / 3.0f));
                float inv = 1.0f / (1.0f + e2);
                size_t t0 = (size_t)tok;
                if (out_size >= 4 * ntok) {
                    out[t0 * 2 + 0] = (float)i1;
                    out[t0 * 2 + 1] = (float)i2;
                    out[(size_t)ntok * 2 + t0 * 2 + 0] = inv;
                    out[(size_t)ntok * 2 + t0 * 2 + 1] = e2 * inv;
                } else if (out_size >= 2 * ntok) {
                    out[t0 * 2 + 0] = (float)i1;
                    out[t0 * 2 + 1] = (float)i2;
                }
                if ((a1 - a2 < THR) || (a2 - a3 < THR)) {
                    int fi = atomicAdd(&g_flagcnt, 1);
                    if (fi < MAXFLAG) g_flaglist[fi] = tok;
                }
            }
        }
    }
}

// ---------------------------------------------------------------------------
// Fixup: exact fp32 recompute of flagged tokens. Grid-strided blocks. (R14)
// ---------------------------------------------------------------------------
__global__ void fixup_kernel(const float* __restrict__ x,
                             const float* __restrict__ proto,
                             float* __restrict__ out, int ntok, int out_size) {
    __shared__ __align__(16) float xs[3][DDIM];
    __shared__ float invn_s[3];
    __shared__ float sl[NEXP];

    int cnt = g_flagcnt;
    if (cnt > MAXFLAG) cnt = MAXFLAG;
    const int t = threadIdx.x, wid = t >> 5, lane = t & 31;

    for (int f = blockIdx.x; f < cnt; f += gridDim.x) {
        int tok = g_flaglist[f];
        int b = tok / SEQ, s = tok - b * SEQ;
        int rows[3] = { s, (s >= 1 ? s - 1 : 0), (s >= 2 ? s - 2 : 0) };

#pragma unroll
        for (int j = 0; j < 3; j++) {
            int fl = t + j * 256;
            int row = fl >> 8, col = fl & 255;
            *reinterpret_cast<float4*>(&xs[row][col * 4]) =
                *reinterpret_cast<const float4*>(
                    x + ((size_t)b * SEQ + rows[row]) * DDIM + col * 4);
        }
        __syncthreads();

        if (wid < 3) {
            float ssum = 0.f;
#pragma unroll
            for (int k2 = 0; k2 < DDIM / 32; k2++) {
                float v = xs[wid][lane + 32 * k2];
                ssum += v * v;
            }
#pragma unroll
            for (int off = 16; off; off >>= 1)
                ssum += __shfl_xor_sync(0xffffffffu, ssum, off);
            if (lane == 0) invn_s[wid] = 1.0f / fmaxf(sqrtf(ssum), 1e-8f);
        }
        __syncthreads();

        float in0 = invn_s[0], in1 = invn_s[1], in2 = invn_s[2];
#pragma unroll
        for (int e = 0; e < 8; e++) {
            int ee = wid * 8 + e;
            const float* pr = proto + (size_t)ee * DDIM;
            float d0 = 0.f, d1 = 0.f, d2 = 0.f;
            for (int k2 = lane; k2 < DDIM; k2 += 32) {
                float pv = pr[k2];
                d0 += xs[0][k2] * pv;
                d1 += xs[1][k2] * pv;
                d2 += xs[2][k2] * pv;
            }
#pragma unroll
            for (int off = 16; off; off >>= 1) {
                d0 += __shfl_xor_sync(0xffffffffu, d0, off);
                d1 += __shfl_xor_sync(0xffffffffu, d1, off);
                d2 += __shfl_xor_sync(0xffffffffu, d2, off);
            }
            if (lane == 0) sl[ee] = d0 * in0 + d1 * in1 + d2 * in2;
        }
        __syncthreads();

        if (t == 0) {
            float a1 = -1e30f, a2 = -1e30f;
            int i1 = 0, i2 = 0;
#pragma unroll
            for (int e = 0; e < NEXP; e++) {
                float v = sl[e];
                if (v > a1) { a2 = a1; i2 = i1; a1 = v; i1 = e; }
                else if (v > a2) { a2 = v; i2 = e; }
            }
            float e2 = expf((a2 - a1) * (1.0f / 3.0f));
            float inv = 1.0f / (1.0f + e2);
            size_t t0 = (size_t)tok;
            if (out_size >= 4 * ntok) {
                out[t0 * 2 + 0] = (float)i1;
                out[t0 * 2 + 1] = (float)i2;
                out[(size_t)ntok * 2 + t0 * 2 + 0] = inv;
                out[(size_t)ntok * 2 + t0 * 2 + 1] = e2 * inv;
            } else if (out_size >= 2 * ntok) {
                out[t0 * 2 + 0] = (float)i1;
                out[t0 * 2 + 1] = (float)i2;
            }
        }
        __syncthreads();
    }
}

// ---------------------------------------------------------------------------
extern "C" void kernel_launch(void* const* d_in, const int* in_sizes, int n_in,
                              void* d_out, int out_size) {
    const float* x     = (const float*)d_in[0];
    const float* proto = (const float*)d_in[1];
    int ntok = in_sizes[2];
    if (ntok > MAXTOK) ntok = MAXTOK;
    float* out = (float*)d_out;

    cudaFuncSetAttribute(gemm_kernel,
                         cudaFuncAttributeMaxDynamicSharedMemorySize, SMEM_TOTAL);

    gemm_kernel<<<(ntok / TM) * KSPLIT, NT, SMEM_TOTAL>>>(x, proto);
    topk_kernel<<<(ntok + TOKPB - 1) / TOKPB, 256>>>(out, ntok, out_size);
    fixup_kernel<<<148, 256>>>(x, proto, out, ntok, out_size);
}